// round 15
// baseline (speedup 1.0000x reference)
#include <cuda_runtime.h>
#include <cuda_fp16.h>
#include <stdint.h>

// Problem constants
#define kB 128
#define kT 2048
#define kI 128
#define kH 256
#define kO 128

#define LDW  392   // LSTM B stride (K=384 padded)
#define LDH  264   // h buffers stride (K=256 padded; uint4-safe)
#define LDX  136   // x buffer stride (K=128 padded; uint4-safe)
#define LDACC 80   // acc row stride in floats (320B: conflict-free elementwise)

// Persistent device state (zero-initialized at module load)
__device__ __half g_h1[2][2][kB][kH];   // [dir][parity][b][h]
__device__ __half g_h2[2][2][kB][kH];
__device__ float  g_hf[2][kB][kH];      // final h2 fp32
__device__ unsigned g_flagA[8][32];     // h1 epoch flags
__device__ unsigned g_flagB[8][32];     // h2 epoch flags
__device__ unsigned g_cnt[4];
__device__ unsigned g_epoch[4];

struct __align__(16) SM {
    __half wL[64][LDW];      // LSTM weights: rows = gate*16+u, cols [0,128)=w1x, [128,384)=w1h
    __half w2x[48][LDH];     // GRU x-weights slice
    __half w2h[48][LDH];     // GRU h-weights slice
    __half xbuf[2][32][LDX]; // double-buffered x_t (fp16)
    __half aH[2][32][LDH];   // staged h1(k), double-buffered by step parity
    __half a2[32][LDH];      // staged h2(k-1) (GRU-private, single buffer)
    float accL[32][LDACC];
    float accX[32][LDACC];
    float accH[32][LDACC];
    float c1[32][16];        // fp32 LSTM cell state (SM-resident)
    float h2l[32][16];       // fp32 GRU hidden (SM-resident)
    float bL[64];
    float b2xs[48];
    float b2hs[48];
};

__device__ __forceinline__ float sigf(float x) {
    return __fdividef(1.0f, 1.0f + __expf(-x));
}
__device__ __forceinline__ float tanhfast(float x) {
    return 2.0f * sigf(2.0f * x) - 1.0f;
}

__device__ __forceinline__ unsigned ld_acq(const unsigned* p) {
    unsigned v;
    asm volatile("ld.acquire.gpu.u32 %0, [%1];" : "=r"(v) : "l"(p) : "memory");
    return v;
}
__device__ __forceinline__ void st_rel(unsigned* p, unsigned v) {
    asm volatile("st.release.gpu.u32 [%0], %1;" :: "l"(p), "r"(v) : "memory");
}
__device__ __forceinline__ void barn(int id, int cnt) {
    asm volatile("bar.sync %0, %1;" :: "r"(id), "r"(cnt) : "memory");
}

// All-CTA sense-reversal barrier (used once before the FC)
__device__ __forceinline__ void gbar_all(int slot, unsigned target) {
    __syncthreads();
    if (threadIdx.x == 0) {
        __threadfence();
        unsigned e = ld_acq(&g_epoch[slot]);
        unsigned old = atomicAdd(&g_cnt[slot], 1u);
        if (old == target - 1u) {
            g_cnt[slot] = 0u;
            __threadfence();
            atomicAdd(&g_epoch[slot], 1u);
        } else {
            while (ld_acq(&g_epoch[slot]) == e) { }
        }
    }
    __syncthreads();
}

// ldmatrix / mma helpers
__device__ __forceinline__ unsigned sptr(const void* p) {
    return (unsigned)__cvta_generic_to_shared(p);
}
__device__ __forceinline__ void lda16x16(unsigned* r, const __half* base, int lda) {
    int lane = threadIdx.x & 31;
    const __half* p = base + (lane & 15) * lda + (lane >> 4) * 8;
    unsigned a = sptr(p);
    asm volatile("ldmatrix.sync.aligned.m8n8.x4.shared.b16 {%0,%1,%2,%3},[%4];"
                 : "=r"(r[0]), "=r"(r[1]), "=r"(r[2]), "=r"(r[3]) : "r"(a));
}
__device__ __forceinline__ void ldb16x8(unsigned* r, const __half* base, int ldb) {
    int lane = threadIdx.x & 31;
    int l = lane & 15;
    const __half* p = base + (l & 7) * ldb + (l >> 3) * 8;
    unsigned a = sptr(p);
    asm volatile("ldmatrix.sync.aligned.m8n8.x2.shared.b16 {%0,%1},[%2];"
                 : "=r"(r[0]), "=r"(r[1]) : "r"(a));
}
__device__ __forceinline__ void mma16816(float* c, const unsigned* a, const unsigned* b) {
    asm volatile("mma.sync.aligned.m16n8k16.row.col.f32.f16.f16.f32 "
                 "{%0,%1,%2,%3},{%4,%5,%6,%7},{%8,%9},{%0,%1,%2,%3};"
                 : "+f"(c[0]), "+f"(c[1]), "+f"(c[2]), "+f"(c[3])
                 : "r"(a[0]), "r"(a[1]), "r"(a[2]), "r"(a[3]), "r"(b[0]), "r"(b[1]));
}
__device__ __forceinline__ void stacc8(float* dst, const float* c) {
    int lane = threadIdx.x & 31;
    int r = lane >> 2, col = (lane & 3) * 2;
    dst[r * LDACC + col]           = c[0];
    dst[r * LDACC + col + 1]       = c[1];
    dst[(r + 8) * LDACC + col]     = c[2];
    dst[(r + 8) * LDACC + col + 1] = c[3];
}

__global__ void __launch_bounds__(512, 1) brnn_kernel(
    const float* __restrict__ x,
    const float* __restrict__ w1x, const float* __restrict__ b1x,
    const float* __restrict__ w1h, const float* __restrict__ b1h,
    const float* __restrict__ w2x, const float* __restrict__ b2x,
    const float* __restrict__ w2h, const float* __restrict__ b2h,
    const float* __restrict__ wo,  const float* __restrict__ bo,
    float* __restrict__ out)
{
    extern __shared__ __align__(16) char smraw[];
    SM& s = *reinterpret_cast<SM*>(smraw);
    const int tid = threadIdx.x;
    const int lane = tid & 31;
    const int d = blockIdx.x >> 6;       // direction
    const int g = blockIdx.x & 63;
    const int bg = g & 3, ng = g >> 2;   // batch-group (32 rows), hidden-group (16 units)
    const int row0 = bg * 32, hu0 = ng * 16;
    const int grp = d * 4 + bg;          // 16-CTA communication group
    const int w = tid >> 5;

    // ---- load weight slices to SMEM (fp16) ----
    for (int idx = tid; idx < 64 * 384; idx += 512) {
        int r = idx / 384, cc = idx - r * 384;
        int gate = r >> 4, u = r & 15;
        int gr = gate * kH + hu0 + u;
        float v = (cc < kI) ? w1x[gr * kI + cc] : w1h[gr * kH + (cc - kI)];
        s.wL[r][cc] = __float2half_rn(v);
    }
    for (int idx = tid; idx < 48 * 256; idx += 512) {
        int r = idx >> 8, cc = idx & 255;
        int gate = r >> 4, u = r & 15;
        int gr = gate * kH + hu0 + u;
        s.w2x[r][cc] = __float2half_rn(w2x[gr * kH + cc]);
        s.w2h[r][cc] = __float2half_rn(w2h[gr * kH + cc]);
    }
    if (tid < 64) {
        int gate = tid >> 4, u = tid & 15;
        int gr = gate * kH + hu0 + u;
        s.bL[tid] = b1x[gr] + b1h[gr];
    }
    if (tid < 48) {
        int gate = tid >> 4, u = tid & 15;
        int gr = gate * kH + hu0 + u;
        s.b2xs[tid] = b2x[gr];
        s.b2hs[tid] = b2h[gr];
    }
    // zero resident state + my slice of parity-0 global state (512 units, 1/thread)
    {
        int b = tid >> 4, u = tid & 15;
        s.c1[b][u] = 0.f;
        s.h2l[b][u] = 0.f;
        g_h1[d][0][row0 + b][hu0 + u] = __float2half_rn(0.f);
        g_h2[d][0][row0 + b][hu0 + u] = __float2half_rn(0.f);
    }
    __threadfence();
    __syncthreads();

    // ---- preload static B fragments into registers ----
    // L warps (0-7): LSTM n8 strip [8w,8w+8): x-part (K=128) + h-part (K=256)
    // G warps (8-13): GRU n8 strip [8(w-8),+8): w2x + w2h (K=256 each)
    unsigned bfx[8][2];    // L only
    unsigned bfa[16][2];   // L: h-part;  G: w2x
    unsigned bfb[16][2];   // G: w2h
    if (w < 8) {
        #pragma unroll
        for (int kk = 0; kk < 8; kk++)
            ldb16x8(bfx[kk], &s.wL[8 * w][kk * 16], LDW);
        #pragma unroll
        for (int kk = 0; kk < 16; kk++)
            ldb16x8(bfa[kk], &s.wL[8 * w][128 + kk * 16], LDW);
    } else if (w < 14) {
        #pragma unroll
        for (int kk = 0; kk < 16; kk++) {
            ldb16x8(bfa[kk], &s.w2x[8 * (w - 8)][kk * 16], LDH);
            ldb16x8(bfb[kk], &s.w2h[8 * (w - 8)][kk * 16], LDH);
        }
    }
    // publish zero-init flags; stage x(0) with L warps
    if (tid == 0) {
        st_rel(&g_flagA[grp][ng], 1u);
        st_rel(&g_flagB[grp][ng], 1u);
    }
    if (tid < 256) {
        const int t0 = d ? (kT - 1) : 0;
        float4 f[4];
        #pragma unroll
        for (int q = 0; q < 4; q++) {
            int idx = tid + 256 * q;
            f[q] = __ldg((const float4*)(x + ((size_t)(row0 + (idx >> 5)) * kT + t0) * kI)
                         + (idx & 31));
        }
        #pragma unroll
        for (int q = 0; q < 4; q++) {
            int idx = tid + 256 * q;
            __half2* dst = (__half2*)&s.xbuf[0][idx >> 5][(idx & 31) * 4];
            dst[0] = __floats2half2_rn(f[q].x, f[q].y);
            dst[1] = __floats2half2_rn(f[q].z, f[q].w);
        }
    }
    __syncthreads();

    // ---- main recurrence (no CTA-wide sync inside; role-scoped barriers) ----
    // L loop (critical): h1.  G loop (slack): h2.  S warps relay staging.
    for (int k = 0; k <= kT; k++) {
        const int par = k & 1;
        const int xb = k & 1;

        if (w < 8) {
            // ================= LSTM warps =================
            float acc[2][4] = {};
            if (k < kT) {
                // x-GEMM from registers-B
                #pragma unroll
                for (int m = 0; m < 2; m++) {
                    #pragma unroll
                    for (int kk = 0; kk < 8; kk++) {
                        unsigned a[4];
                        lda16x16(a, &s.xbuf[xb][m * 16][kk * 16], LDX);
                        mma16816(acc[m], a, bfx[kk]);
                    }
                }
                // stage x(k+1) -> xbuf[xb^1] (ordered vs next read by barn3 below)
                if (k + 1 < kT) {
                    const int t = d ? (kT - 2 - k) : (k + 1);
                    float4 f[4];
                    #pragma unroll
                    for (int q = 0; q < 4; q++) {
                        int idx = tid + 256 * q;
                        f[q] = __ldg((const float4*)(x +
                                ((size_t)(row0 + (idx >> 5)) * kT + t) * kI) + (idx & 31));
                    }
                    #pragma unroll
                    for (int q = 0; q < 4; q++) {
                        int idx = tid + 256 * q;
                        __half2* dst = (__half2*)&s.xbuf[xb ^ 1][idx >> 5][(idx & 31) * 4];
                        dst[0] = __floats2half2_rn(f[q].x, f[q].y);
                        dst[1] = __floats2half2_rn(f[q].z, f[q].w);
                    }
                }
            }
            barn(1, 320);   // A1: aH[par] staged by S warps
            if (k < kT) {
                #pragma unroll
                for (int m = 0; m < 2; m++) {
                    #pragma unroll
                    for (int kk = 0; kk < 16; kk++) {
                        unsigned a[4];
                        lda16x16(a, &s.aH[par][m * 16][kk * 16], LDH);
                        mma16816(acc[m], a, bfa[kk]);
                    }
                }
                #pragma unroll
                for (int m = 0; m < 2; m++)
                    stacc8(&s.accL[m * 16][8 * w], acc[m]);
            }
            barn(3, 256);
            if (k < kT) {
                // LSTM eltwise: 256 thr, 2 units each
                const int b = tid >> 3, u0 = (tid & 7) * 2;
                float h1v[2];
                #pragma unroll
                for (int q = 0; q < 2; q++) {
                    int u = u0 + q;
                    float ig = sigf(s.accL[b][u]           + s.bL[u]);
                    float fg = sigf(s.accL[b][16 + u]      + s.bL[16 + u]);
                    float gg = tanhfast(s.accL[b][32 + u]  + s.bL[32 + u]);
                    float og = sigf(s.accL[b][48 + u]      + s.bL[48 + u]);
                    float c  = s.c1[b][u] * fg + ig * gg;
                    s.c1[b][u] = c;
                    h1v[q] = og * tanhfast(c);
                }
                *(__half2*)&g_h1[d][par ^ 1][row0 + b][hu0 + u0] =
                    __floats2half2_rn(h1v[0], h1v[1]);
                __threadfence();
            }
            barn(3, 256);
            if (tid == 0 && k < kT)
                st_rel(&g_flagA[grp][ng], (unsigned)(k + 2));
        } else if (w < 14) {
            // ================= GRU warps =================
            const int tg = tid - 256;
            barn(2, 256);   // A2 with S: aH[par] ready (placed after S released L)
            float accx[2][4] = {}, acch[2][4] = {};
            // poll flagB (warp 8 lanes 0-15) while others run x-GEMM
            if (w == 8 && lane < 16) {
                const unsigned* fp = &g_flagB[grp][lane];
                const unsigned ep = (unsigned)(k + 1);
                while (ld_acq(fp) < ep) { }
            }
            #pragma unroll
            for (int m = 0; m < 2; m++) {
                #pragma unroll
                for (int kk = 0; kk < 16; kk++) {
                    unsigned a[4];
                    lda16x16(a, &s.aH[par][m * 16][kk * 16], LDH);
                    mma16816(accx[m], a, bfa[kk]);
                }
            }
            barn(7, 192);   // pollB done (and prev a2 reads complete via program order)
            // stage h2(k-1) -> a2 (192 thr, batched predicated)
            {
                const uint4* s2 = (const uint4*)&g_h2[d][par][row0][0];
                uint4 v2[6];
                #pragma unroll
                for (int q = 0; q < 6; q++) {
                    int idx = tg + 192 * q;
                    if (idx < 1024) v2[q] = __ldcg(s2 + idx);
                }
                #pragma unroll
                for (int q = 0; q < 6; q++) {
                    int idx = tg + 192 * q;
                    if (idx < 1024) *((uint4*)&s.a2[idx >> 5][0] + (idx & 31)) = v2[q];
                }
            }
            barn(7, 192);   // a2 staged
            #pragma unroll
            for (int m = 0; m < 2; m++) {
                #pragma unroll
                for (int kk = 0; kk < 16; kk++) {
                    unsigned a[4];
                    lda16x16(a, &s.a2[m * 16][kk * 16], LDH);
                    mma16816(acch[m], a, bfb[kk]);
                }
            }
            #pragma unroll
            for (int m = 0; m < 2; m++) {
                stacc8(&s.accX[m * 16][8 * (w - 8)], accx[m]);
                stacc8(&s.accH[m * 16][8 * (w - 8)], acch[m]);
            }
            barn(4, 192);
            // GRU eltwise: 192 thr cover 256 unit-pairs
            for (int p = tg; p < 256; p += 192) {
                const int b = p >> 3, u0 = (p & 7) * 2;
                float h2v[2];
                #pragma unroll
                for (int q = 0; q < 2; q++) {
                    int u = u0 + q;
                    float rr = sigf(s.accX[b][u]      + s.b2xs[u]      + s.accH[b][u]      + s.b2hs[u]);
                    float zz = sigf(s.accX[b][16 + u] + s.b2xs[16 + u] + s.accH[b][16 + u] + s.b2hs[16 + u]);
                    float hn = s.accH[b][32 + u] + s.b2hs[32 + u];
                    float nn = tanhfast(s.accX[b][32 + u] + s.b2xs[32 + u] + rr * hn);
                    float h2 = zz * s.h2l[b][u] + (1.f - zz) * nn;
                    s.h2l[b][u] = h2;
                    h2v[q] = h2;
                }
                *(__half2*)&g_h2[d][par ^ 1][row0 + b][hu0 + u0] =
                    __floats2half2_rn(h2v[0], h2v[1]);
                if (k == kT) {
                    g_hf[d][row0 + b][hu0 + u0]     = h2v[0];
                    g_hf[d][row0 + b][hu0 + u0 + 1] = h2v[1];
                }
            }
            __threadfence();
            barn(4, 192);
            if (tid == 256 && k < kT)
                st_rel(&g_flagB[grp][ng], (unsigned)(k + 2));
        } else {
            // ================= stage warps (14-15) =================
            const int tl = tid - 448;
            if (w == 14 && lane < 16) {
                const unsigned* fp = &g_flagA[grp][lane];
                const unsigned ep = (unsigned)(k + 1);
                while (ld_acq(fp) < ep) { }
            }
            barn(6, 64);
            // stage h1(k) -> aH[par]: 64 thr, 16 uint4 each in two batched rounds
            {
                const uint4* s1 = (const uint4*)&g_h1[d][par][row0][0];
                #pragma unroll
                for (int rnd = 0; rnd < 2; rnd++) {
                    uint4 v[8];
                    #pragma unroll
                    for (int q = 0; q < 8; q++)
                        v[q] = __ldcg(s1 + tl + 64 * q + 512 * rnd);
                    #pragma unroll
                    for (int q = 0; q < 8; q++) {
                        int idx = tl + 64 * q + 512 * rnd;
                        *((uint4*)&s.aH[par][idx >> 5][0] + (idx & 31)) = v[q];
                    }
                }
            }
            barn(1, 320);   // release LSTM warps
            barn(2, 256);   // release GRU warps (after L, so GRU lag can't block L)
        }
    }

    // ---- all-CTA barrier, reset flags for next graph replay ----
    __threadfence();
    gbar_all(2, 128);
    if (tid == 0) { g_flagA[grp][ng] = 0; g_flagB[grp][ng] = 0; }

    // ---- final FC: out = [h_fwd | h_bwd] @ wo^T + bo ----
    if (blockIdx.x < 16) {
        float* sh = (float*)&s;              // reuse SMEM: [8][512]
        int b0r = blockIdx.x * 8;
        for (int idx = tid; idx < 8 * 512; idx += 512) {
            int br = idx >> 9, jj = idx & 511;
            sh[idx] = (jj < 256) ? __ldcg(&g_hf[0][b0r + br][jj])
                                 : __ldcg(&g_hf[1][b0r + br][jj - 256]);
        }
        __syncthreads();
        for (int it = tid; it < 8 * 128; it += 512) {
            int br = it >> 7, o = it & 127;
            float acc = bo[o];
            const float* wrow = wo + o * 512;
            const float* hrow = sh + br * 512;
            #pragma unroll 8
            for (int jj = 0; jj < 512; jj++) acc += hrow[jj] * wrow[jj];
            out[(size_t)(b0r + br) * kO + o] = acc;
        }
    }
}

extern "C" void kernel_launch(void* const* d_in, const int* in_sizes, int n_in,
                              void* d_out, int out_size)
{
    const float* x   = (const float*)d_in[0];
    const float* w1x = (const float*)d_in[1];
    const float* b1x = (const float*)d_in[2];
    const float* w1h = (const float*)d_in[3];
    const float* b1h = (const float*)d_in[4];
    const float* w2x = (const float*)d_in[5];
    const float* b2x = (const float*)d_in[6];
    const float* w2h = (const float*)d_in[7];
    const float* b2h = (const float*)d_in[8];
    const float* wo  = (const float*)d_in[9];
    const float* bo  = (const float*)d_in[10];

    cudaFuncSetAttribute(brnn_kernel, cudaFuncAttributeMaxDynamicSharedMemorySize,
                         (int)sizeof(SM));
    brnn_kernel<<<128, 512, sizeof(SM)>>>(x, w1x, b1x, w1h, b1h,
                                          w2x, b2x, w2h, b2h, wo, bo,
                                          (float*)d_out);
}

// round 16
// speedup vs baseline: 1.0446x; 1.0446x over previous
#include <cuda_runtime.h>
#include <cuda_fp16.h>
#include <stdint.h>

// Problem constants
#define kB 128
#define kT 2048
#define kI 128
#define kH 256
#define kO 128

#define LDW  392   // LSTM B stride (K=384 padded)
#define LDH  264   // h buffers stride (K=256 padded; uint4-safe)
#define LDX  136   // x buffer stride (K=128 padded; uint4-safe)
#define LDACC 80   // acc row stride in floats (320B: conflict-free elementwise)

// Persistent device state (zero-initialized at module load)
__device__ __half g_h1[2][2][kB][kH];   // [dir][parity][b][h]
__device__ __half g_h2[2][2][kB][kH];
__device__ float  g_hf[2][kB][kH];      // final h2 fp32
__device__ unsigned g_flag[8][32];      // [group][ng] epoch flags (reset at kernel end)
__device__ unsigned g_cnt[4];
__device__ unsigned g_epoch[4];

struct __align__(16) SM {
    __half wL[64][LDW];      // LSTM weights: rows = gate*16+u, cols [0,128)=w1x, [128,384)=w1h
    __half w2x[48][LDH];     // GRU x-weights slice
    __half w2h[48][LDH];     // GRU h-weights slice
    __half xbuf[2][32][LDX]; // double-buffered x_t (fp16)
    __half aH[32][LDH];      // staged h1(k)
    __half a2[32][LDH];      // staged h2(k-1)
    float accL[32][LDACC];
    float accX[32][LDACC];
    float accH[32][LDACC];
    float c1[32][16];        // fp32 LSTM cell state (SM-resident)
    float h2l[32][16];       // fp32 GRU hidden (SM-resident)
    float bL[64];
    float b2xs[48];
    float b2hs[48];
};

__device__ __forceinline__ float sigf(float x) {
    return __fdividef(1.0f, 1.0f + __expf(-x));
}
__device__ __forceinline__ float tanhfast(float x) {
    return 2.0f * sigf(2.0f * x) - 1.0f;
}

__device__ __forceinline__ unsigned ld_acq(const unsigned* p) {
    unsigned v;
    asm volatile("ld.acquire.gpu.u32 %0, [%1];" : "=r"(v) : "l"(p) : "memory");
    return v;
}
__device__ __forceinline__ void st_rel(unsigned* p, unsigned v) {
    asm volatile("st.release.gpu.u32 [%0], %1;" :: "l"(p), "r"(v) : "memory");
}
__device__ __forceinline__ void barn(int id, int cnt) {
    asm volatile("bar.sync %0, %1;" :: "r"(id), "r"(cnt) : "memory");
}

// All-CTA sense-reversal barrier (used once before the FC)
__device__ __forceinline__ void gbar_all(int slot, unsigned target) {
    __syncthreads();
    if (threadIdx.x == 0) {
        __threadfence();
        unsigned e = ld_acq(&g_epoch[slot]);
        unsigned old = atomicAdd(&g_cnt[slot], 1u);
        if (old == target - 1u) {
            g_cnt[slot] = 0u;
            __threadfence();
            atomicAdd(&g_epoch[slot], 1u);
        } else {
            while (ld_acq(&g_epoch[slot]) == e) { }
        }
    }
    __syncthreads();
}

// ldmatrix / mma helpers
__device__ __forceinline__ unsigned sptr(const void* p) {
    return (unsigned)__cvta_generic_to_shared(p);
}
__device__ __forceinline__ void lda16x16(unsigned* r, const __half* base, int lda) {
    int lane = threadIdx.x & 31;
    const __half* p = base + (lane & 15) * lda + (lane >> 4) * 8;
    unsigned a = sptr(p);
    asm volatile("ldmatrix.sync.aligned.m8n8.x4.shared.b16 {%0,%1,%2,%3},[%4];"
                 : "=r"(r[0]), "=r"(r[1]), "=r"(r[2]), "=r"(r[3]) : "r"(a));
}
__device__ __forceinline__ void ldb16x8(unsigned* r, const __half* base, int ldb) {
    int lane = threadIdx.x & 31;
    int l = lane & 15;
    const __half* p = base + (l & 7) * ldb + (l >> 3) * 8;
    unsigned a = sptr(p);
    asm volatile("ldmatrix.sync.aligned.m8n8.x2.shared.b16 {%0,%1},[%2];"
                 : "=r"(r[0]), "=r"(r[1]) : "r"(a));
}
__device__ __forceinline__ void mma16816(float* c, const unsigned* a, const unsigned* b) {
    asm volatile("mma.sync.aligned.m16n8k16.row.col.f32.f16.f16.f32 "
                 "{%0,%1,%2,%3},{%4,%5,%6,%7},{%8,%9},{%0,%1,%2,%3};"
                 : "+f"(c[0]), "+f"(c[1]), "+f"(c[2]), "+f"(c[3])
                 : "r"(a[0]), "r"(a[1]), "r"(a[2]), "r"(a[3]), "r"(b[0]), "r"(b[1]));
}
__device__ __forceinline__ void stacc(float* dst, const float* c) {
    int lane = threadIdx.x & 31;
    int r = lane >> 2, col = (lane & 3) * 2;
    dst[r * LDACC + col]           = c[0];
    dst[r * LDACC + col + 1]       = c[1];
    dst[(r + 8) * LDACC + col]     = c[2];
    dst[(r + 8) * LDACC + col + 1] = c[3];
}

// x staging: 192 threads (tl in [0,192)), 1024 float4s, batched predicated unroll.
__device__ __forceinline__ void stage_x_192(SM& s, const float* __restrict__ x,
                                            int buf, int t, int row0, int tl) {
    float4 f[6];
    #pragma unroll
    for (int q = 0; q < 6; q++) {
        int idx = tl + 192 * q;
        if (idx < 1024)
            f[q] = __ldg((const float4*)(x + ((size_t)(row0 + (idx >> 5)) * kT + t) * kI)
                         + (idx & 31));
    }
    #pragma unroll
    for (int q = 0; q < 6; q++) {
        int idx = tl + 192 * q;
        if (idx < 1024) {
            __half2* dst = (__half2*)&s.xbuf[buf][idx >> 5][(idx & 31) * 4];
            dst[0] = __floats2half2_rn(f[q].x, f[q].y);
            dst[1] = __floats2half2_rn(f[q].z, f[q].w);
        }
    }
}

__global__ void __launch_bounds__(512, 1) brnn_kernel(
    const float* __restrict__ x,
    const float* __restrict__ w1x, const float* __restrict__ b1x,
    const float* __restrict__ w1h, const float* __restrict__ b1h,
    const float* __restrict__ w2x, const float* __restrict__ b2x,
    const float* __restrict__ w2h, const float* __restrict__ b2h,
    const float* __restrict__ wo,  const float* __restrict__ bo,
    float* __restrict__ out)
{
    extern __shared__ __align__(16) char smraw[];
    SM& s = *reinterpret_cast<SM*>(smraw);
    const int tid = threadIdx.x;
    const int lane = tid & 31;
    const int d = blockIdx.x >> 6;       // direction
    const int g = blockIdx.x & 63;
    const int bg = g & 3, ng = g >> 2;   // batch-group (32 rows), hidden-group (16 units)
    const int row0 = bg * 32, hu0 = ng * 16;
    const int grp = d * 4 + bg;          // 16-CTA communication group
    const int w = tid >> 5;

    // ---- load weight slices to SMEM (fp16) ----
    for (int idx = tid; idx < 64 * 384; idx += 512) {
        int r = idx / 384, cc = idx - r * 384;
        int gate = r >> 4, u = r & 15;
        int gr = gate * kH + hu0 + u;
        float v = (cc < kI) ? w1x[gr * kI + cc] : w1h[gr * kH + (cc - kI)];
        s.wL[r][cc] = __float2half_rn(v);
    }
    for (int idx = tid; idx < 48 * 256; idx += 512) {
        int r = idx >> 8, cc = idx & 255;
        int gate = r >> 4, u = r & 15;
        int gr = gate * kH + hu0 + u;
        s.w2x[r][cc] = __float2half_rn(w2x[gr * kH + cc]);
        s.w2h[r][cc] = __float2half_rn(w2h[gr * kH + cc]);
    }
    if (tid < 64) {
        int gate = tid >> 4, u = tid & 15;
        int gr = gate * kH + hu0 + u;
        s.bL[tid] = b1x[gr] + b1h[gr];
    }
    if (tid < 48) {
        int gate = tid >> 4, u = tid & 15;
        int gr = gate * kH + hu0 + u;
        s.b2xs[tid] = b2x[gr];
        s.b2hs[tid] = b2h[gr];
    }
    // zero resident state + my slice of parity-0 global state (512 units, 1/thread)
    {
        int b = tid >> 4, u = tid & 15;
        s.c1[b][u] = 0.f;
        s.h2l[b][u] = 0.f;
        g_h1[d][0][row0 + b][hu0 + u] = __float2half_rn(0.f);
        g_h2[d][0][row0 + b][hu0 + u] = __float2half_rn(0.f);
    }
    __threadfence();
    __syncthreads();

    // ---- preload static B fragments into registers (GEMM warps 0-9) ----
    unsigned bfrag[2][16][2];
    if (w < 10) {
        #pragma unroll
        for (int sf = 0; sf < 2; sf++) {
            #pragma unroll
            for (int kk = 0; kk < 16; kk++) {
                if (w < 4)
                    ldb16x8(bfrag[sf][kk], &s.wL[(2 * w + sf) * 8][128 + kk * 16], LDW);
                else if (w < 7)
                    ldb16x8(bfrag[sf][kk], &s.w2x[(2 * (w - 4) + sf) * 8][kk * 16], LDH);
                else
                    ldb16x8(bfrag[sf][kk], &s.w2h[(2 * (w - 7) + sf) * 8][kk * 16], LDH);
            }
        }
    }
    // publish zero-init flag; stage x(0) with warps 10-15 (pre-loop, off critical path)
    if (tid == 0) st_rel(&g_flag[grp][ng], 1u);
    if (w >= 10)
        stage_x_192(s, x, 0, d ? (kT - 1) : 0, row0, tid - 320);
    __syncthreads();

    // ---- main recurrence: iteration k computes h1(k+1) and h2(k) ----
    for (int k = 0; k <= kT; k++) {
        const int par = k & 1;
        const int xb = k & 1;
        float acc[2][2][4] = {};   // [m-tile][strip][frag]

        if (w < 4) {
            // -------- Phase A: LSTM x-part GEMM (overlaps poll/stage) --------
            if (k < kT) {
                #pragma unroll
                for (int m = 0; m < 2; m++) {
                    #pragma unroll
                    for (int kk = 0; kk < 8; kk++) {
                        unsigned a[4];
                        lda16x16(a, &s.xbuf[xb][m * 16][kk * 16], LDX);
                        #pragma unroll
                        for (int sf = 0; sf < 2; sf++) {
                            unsigned b[2];
                            ldb16x8(b, &s.wL[(2 * w + sf) * 8][kk * 16], LDW);
                            mma16816(acc[m][sf], a, b);
                        }
                    }
                }
            }
        } else if (w < 10) {
            // -------- Phase A: GRU warps prefetch x(k+1) (they were idle here) ----
            if (k + 1 < kT) {
                const int t = d ? (kT - 2 - k) : (k + 1);
                stage_x_192(s, x, xb ^ 1, t, row0, tid - 128);
            }
        } else {
            const int tl = tid - 320;
            // poll group flags IMMEDIATELY (warp 10, lanes 0-15) — no x work ahead
            if (w == 10 && lane < 16) {
                const unsigned* fp = &g_flag[grp][lane];
                const unsigned ep = (unsigned)(k + 1);
                while (ld_acq(fp) < ep) { }
            }
            barn(1, 192);
            // stage h1(k) -> aH, h2(k-1) -> a2 : batched predicated unroll (MLP~12)
            {
                const uint4* s1 = (const uint4*)&g_h1[d][par][row0][0];
                const uint4* s2 = (const uint4*)&g_h2[d][par][row0][0];
                uint4 v1[6], v2[6];
                #pragma unroll
                for (int q = 0; q < 6; q++) {
                    int idx = tl + 192 * q;
                    if (idx < 1024) v1[q] = __ldcg(s1 + idx);
                }
                #pragma unroll
                for (int q = 0; q < 6; q++) {
                    int idx = tl + 192 * q;
                    if (idx < 1024) v2[q] = __ldcg(s2 + idx);
                }
                #pragma unroll
                for (int q = 0; q < 6; q++) {
                    int idx = tl + 192 * q;
                    if (idx < 1024) *((uint4*)&s.aH[idx >> 5][0] + (idx & 31)) = v1[q];
                }
                #pragma unroll
                for (int q = 0; q < 6; q++) {
                    int idx = tl + 192 * q;
                    if (idx < 1024) *((uint4*)&s.a2[idx >> 5][0] + (idx & 31)) = v2[q];
                }
            }
        }
        __syncthreads();   // sync1

        // -------- Phase B: h-dependent GEMMs (B from registers) --------
        if (w < 4) {
            if (k < kT) {
                #pragma unroll
                for (int m = 0; m < 2; m++) {
                    #pragma unroll
                    for (int kk = 0; kk < 16; kk++) {
                        unsigned a[4];
                        lda16x16(a, &s.aH[m * 16][kk * 16], LDH);
                        #pragma unroll
                        for (int sf = 0; sf < 2; sf++)
                            mma16816(acc[m][sf], a, bfrag[sf][kk]);
                    }
                }
                #pragma unroll
                for (int m = 0; m < 2; m++)
                    #pragma unroll
                    for (int sf = 0; sf < 2; sf++)
                        stacc(&s.accL[m * 16][(2 * w + sf) * 8], acc[m][sf]);
            }
        } else if (w < 10) {
            const bool isx = (w < 7);
            const int j = isx ? (w - 4) : (w - 7);
            const __half* A0 = isx ? &s.aH[0][0] : &s.a2[0][0];
            #pragma unroll
            for (int m = 0; m < 2; m++) {
                #pragma unroll
                for (int kk = 0; kk < 16; kk++) {
                    unsigned a[4];
                    lda16x16(a, A0 + (m * 16) * LDH + kk * 16, LDH);
                    #pragma unroll
                    for (int sf = 0; sf < 2; sf++)
                        mma16816(acc[m][sf], a, bfrag[sf][kk]);
                }
            }
            float* dstbase = isx ? &s.accX[0][0] : &s.accH[0][0];
            #pragma unroll
            for (int m = 0; m < 2; m++)
                #pragma unroll
                for (int sf = 0; sf < 2; sf++)
                    stacc(dstbase + (m * 16) * LDACC + (2 * j + sf) * 8, acc[m][sf]);
        }
        __syncthreads();   // sync2

        // -------- Phase C: eltwise split — w0-7 LSTM, w8-15 GRU (parallel) --------
        if (w < 8) {
            if (k < kT) {
                const int b = tid >> 3, u0 = (tid & 7) * 2;
                float h1v[2];
                #pragma unroll
                for (int q = 0; q < 2; q++) {
                    int u = u0 + q;
                    float ig = sigf(s.accL[b][u]           + s.bL[u]);
                    float fg = sigf(s.accL[b][16 + u]      + s.bL[16 + u]);
                    float gg = tanhfast(s.accL[b][32 + u]  + s.bL[32 + u]);
                    float og = sigf(s.accL[b][48 + u]      + s.bL[48 + u]);
                    float c  = s.c1[b][u] * fg + ig * gg;
                    s.c1[b][u] = c;
                    h1v[q] = og * tanhfast(c);
                }
                *(__half2*)&g_h1[d][par ^ 1][row0 + b][hu0 + u0] =
                    __floats2half2_rn(h1v[0], h1v[1]);
            }
        } else {
            const int tc = tid - 256;
            const int b = tc >> 3, u0 = (tc & 7) * 2;
            float h2v[2];
            #pragma unroll
            for (int q = 0; q < 2; q++) {
                int u = u0 + q;
                float rr = sigf(s.accX[b][u]      + s.b2xs[u]      + s.accH[b][u]      + s.b2hs[u]);
                float zz = sigf(s.accX[b][16 + u] + s.b2xs[16 + u] + s.accH[b][16 + u] + s.b2hs[16 + u]);
                float hn = s.accH[b][32 + u] + s.b2hs[32 + u];
                float nn = tanhfast(s.accX[b][32 + u] + s.b2xs[32 + u] + rr * hn);
                float h2 = zz * s.h2l[b][u] + (1.f - zz) * nn;
                s.h2l[b][u] = h2;
                h2v[q] = h2;
            }
            *(__half2*)&g_h2[d][par ^ 1][row0 + b][hu0 + u0] =
                __floats2half2_rn(h2v[0], h2v[1]);
            if (k == kT) {
                g_hf[d][row0 + b][hu0 + u0]     = h2v[0];
                g_hf[d][row0 + b][hu0 + u0 + 1] = h2v[1];
            }
        }

        __syncthreads();   // sync3 — makes all eltwise writes CTA-visible
        if (tid == 0 && k < kT) {
            __threadfence();                     // cumulativity: promote to gpu scope
            st_rel(&g_flag[grp][ng], (unsigned)(k + 2));
        }
        if (k == kT) break;
    }

    // ---- all-CTA barrier, reset flags for next graph replay ----
    __threadfence();
    gbar_all(2, 128);
    if (tid == 0) g_flag[grp][ng] = 0;

    // ---- final FC: out = [h_fwd | h_bwd] @ wo^T + bo ----
    if (blockIdx.x < 16) {
        float* sh = (float*)&s;              // reuse SMEM: [8][512]
        int b0r = blockIdx.x * 8;
        for (int idx = tid; idx < 8 * 512; idx += 512) {
            int br = idx >> 9, jj = idx & 511;
            sh[idx] = (jj < 256) ? __ldcg(&g_hf[0][b0r + br][jj])
                                 : __ldcg(&g_hf[1][b0r + br][jj - 256]);
        }
        __syncthreads();
        for (int it = tid; it < 8 * 128; it += 512) {
            int br = it >> 7, o = it & 127;
            float acc = bo[o];
            const float* wrow = wo + o * 512;
            const float* hrow = sh + br * 512;
            #pragma unroll 8
            for (int jj = 0; jj < 512; jj++) acc += hrow[jj] * wrow[jj];
            out[(size_t)(b0r + br) * kO + o] = acc;
        }
    }
}

extern "C" void kernel_launch(void* const* d_in, const int* in_sizes, int n_in,
                              void* d_out, int out_size)
{
    const float* x   = (const float*)d_in[0];
    const float* w1x = (const float*)d_in[1];
    const float* b1x = (const float*)d_in[2];
    const float* w1h = (const float*)d_in[3];
    const float* b1h = (const float*)d_in[4];
    const float* w2x = (const float*)d_in[5];
    const float* b2x = (const float*)d_in[6];
    const float* w2h = (const float*)d_in[7];
    const float* b2h = (const float*)d_in[8];
    const float* wo  = (const float*)d_in[9];
    const float* bo  = (const float*)d_in[10];

    cudaFuncSetAttribute(brnn_kernel, cudaFuncAttributeMaxDynamicSharedMemorySize,
                         (int)sizeof(SM));
    brnn_kernel<<<128, 512, sizeof(SM)>>>(x, w1x, b1x, w1h, b1h,
                                          w2x, b2x, w2h, b2h, wo, bo,
                                          (float*)d_out);
}

// round 17
// speedup vs baseline: 1.1944x; 1.1433x over previous
#include <cuda_runtime.h>
#include <cuda_fp16.h>
#include <stdint.h>

// Problem constants
#define kB 128
#define kT 2048
#define kI 128
#define kH 256
#define kO 128

#define LDW  392   // LSTM B stride (K=384 padded)
#define LDH  264   // h buffers stride (K=256 padded; uint4-safe)
#define LDX  136   // x buffer stride (K=128 padded; uint4-safe)
#define LDACC 80   // acc row stride in floats (320B: conflict-free elementwise)

// Persistent device state (zero-initialized at module load)
__device__ __half g_h1[2][2][kB][kH];   // [dir][parity][b][h]
__device__ __half g_h2[2][2][kB][kH];
__device__ float  g_hf[2][kB][kH];      // final h2 fp32
__device__ unsigned g_flag[8][32][32];  // [group][ng][pad]: one 128B line per flag
__device__ unsigned g_cnt[4];
__device__ unsigned g_epoch[4];

struct __align__(16) SM {
    __half wL[64][LDW];      // LSTM weights: rows = gate*16+u, cols [0,128)=w1x, [128,384)=w1h
    __half w2x[48][LDH];     // GRU x-weights slice
    __half w2h[48][LDH];     // GRU h-weights slice
    __half xbuf[2][32][LDX]; // double-buffered x_t (fp16)
    __half aH[32][LDH];      // staged h1(k)
    __half a2[32][LDH];      // staged h2(k-1)
    float accL[32][LDACC];
    float accX[32][LDACC];
    float accH[32][LDACC];
    float c1[32][16];        // fp32 LSTM cell state (SM-resident)
    float h2l[32][16];       // fp32 GRU hidden (SM-resident)
    float bL[64];
    float b2xs[48];
    float b2hs[48];
};

__device__ __forceinline__ float sigf(float x) {
    return __fdividef(1.0f, 1.0f + __expf(-x));
}
__device__ __forceinline__ float tanhfast(float x) {
    return 2.0f * sigf(2.0f * x) - 1.0f;
}

__device__ __forceinline__ unsigned ld_acq(const unsigned* p) {
    unsigned v;
    asm volatile("ld.acquire.gpu.u32 %0, [%1];" : "=r"(v) : "l"(p) : "memory");
    return v;
}
__device__ __forceinline__ void st_rel(unsigned* p, unsigned v) {
    asm volatile("st.release.gpu.u32 [%0], %1;" :: "l"(p), "r"(v) : "memory");
}
__device__ __forceinline__ void barn(int id, int cnt) {
    asm volatile("bar.sync %0, %1;" :: "r"(id), "r"(cnt) : "memory");
}

// All-CTA sense-reversal barrier (used once before the FC)
__device__ __forceinline__ void gbar_all(int slot, unsigned target) {
    __syncthreads();
    if (threadIdx.x == 0) {
        __threadfence();
        unsigned e = ld_acq(&g_epoch[slot]);
        unsigned old = atomicAdd(&g_cnt[slot], 1u);
        if (old == target - 1u) {
            g_cnt[slot] = 0u;
            __threadfence();
            atomicAdd(&g_epoch[slot], 1u);
        } else {
            while (ld_acq(&g_epoch[slot]) == e) { }
        }
    }
    __syncthreads();
}

// ldmatrix / mma helpers
__device__ __forceinline__ unsigned sptr(const void* p) {
    return (unsigned)__cvta_generic_to_shared(p);
}
__device__ __forceinline__ void lda16x16(unsigned* r, const __half* base, int lda) {
    int lane = threadIdx.x & 31;
    const __half* p = base + (lane & 15) * lda + (lane >> 4) * 8;
    unsigned a = sptr(p);
    asm volatile("ldmatrix.sync.aligned.m8n8.x4.shared.b16 {%0,%1,%2,%3},[%4];"
                 : "=r"(r[0]), "=r"(r[1]), "=r"(r[2]), "=r"(r[3]) : "r"(a));
}
__device__ __forceinline__ void ldb16x8(unsigned* r, const __half* base, int ldb) {
    int lane = threadIdx.x & 31;
    int l = lane & 15;
    const __half* p = base + (l & 7) * ldb + (l >> 3) * 8;
    unsigned a = sptr(p);
    asm volatile("ldmatrix.sync.aligned.m8n8.x2.shared.b16 {%0,%1},[%2];"
                 : "=r"(r[0]), "=r"(r[1]) : "r"(a));
}
__device__ __forceinline__ void mma16816(float* c, const unsigned* a, const unsigned* b) {
    asm volatile("mma.sync.aligned.m16n8k16.row.col.f32.f16.f16.f32 "
                 "{%0,%1,%2,%3},{%4,%5,%6,%7},{%8,%9},{%0,%1,%2,%3};"
                 : "+f"(c[0]), "+f"(c[1]), "+f"(c[2]), "+f"(c[3])
                 : "r"(a[0]), "r"(a[1]), "r"(a[2]), "r"(a[3]), "r"(b[0]), "r"(b[1]));
}
__device__ __forceinline__ void stacc(float* dst, const float* c) {
    int lane = threadIdx.x & 31;
    int r = lane >> 2, col = (lane & 3) * 2;
    dst[r * LDACC + col]           = c[0];
    dst[r * LDACC + col + 1]       = c[1];
    dst[(r + 8) * LDACC + col]     = c[2];
    dst[(r + 8) * LDACC + col + 1] = c[3];
}

// x staging: 192 threads (tl in [0,192)), 1024 float4s, batched predicated unroll.
__device__ __forceinline__ void stage_x_192(SM& s, const float* __restrict__ x,
                                            int buf, int t, int row0, int tl) {
    float4 f[6];
    #pragma unroll
    for (int q = 0; q < 6; q++) {
        int idx = tl + 192 * q;
        if (idx < 1024)
            f[q] = __ldg((const float4*)(x + ((size_t)(row0 + (idx >> 5)) * kT + t) * kI)
                         + (idx & 31));
    }
    #pragma unroll
    for (int q = 0; q < 6; q++) {
        int idx = tl + 192 * q;
        if (idx < 1024) {
            __half2* dst = (__half2*)&s.xbuf[buf][idx >> 5][(idx & 31) * 4];
            dst[0] = __floats2half2_rn(f[q].x, f[q].y);
            dst[1] = __floats2half2_rn(f[q].z, f[q].w);
        }
    }
}

__global__ void __launch_bounds__(512, 1) brnn_kernel(
    const float* __restrict__ x,
    const float* __restrict__ w1x, const float* __restrict__ b1x,
    const float* __restrict__ w1h, const float* __restrict__ b1h,
    const float* __restrict__ w2x, const float* __restrict__ b2x,
    const float* __restrict__ w2h, const float* __restrict__ b2h,
    const float* __restrict__ wo,  const float* __restrict__ bo,
    float* __restrict__ out)
{
    extern __shared__ __align__(16) char smraw[];
    SM& s = *reinterpret_cast<SM*>(smraw);
    const int tid = threadIdx.x;
    const int lane = tid & 31;
    const int d = blockIdx.x >> 6;       // direction
    const int g = blockIdx.x & 63;
    const int bg = g & 3, ng = g >> 2;   // batch-group (32 rows), hidden-group (16 units)
    const int row0 = bg * 32, hu0 = ng * 16;
    const int grp = d * 4 + bg;          // 16-CTA communication group
    const int w = tid >> 5;

    // ---- load weight slices to SMEM (fp16) ----
    for (int idx = tid; idx < 64 * 384; idx += 512) {
        int r = idx / 384, cc = idx - r * 384;
        int gate = r >> 4, u = r & 15;
        int gr = gate * kH + hu0 + u;
        float v = (cc < kI) ? w1x[gr * kI + cc] : w1h[gr * kH + (cc - kI)];
        s.wL[r][cc] = __float2half_rn(v);
    }
    for (int idx = tid; idx < 48 * 256; idx += 512) {
        int r = idx >> 8, cc = idx & 255;
        int gate = r >> 4, u = r & 15;
        int gr = gate * kH + hu0 + u;
        s.w2x[r][cc] = __float2half_rn(w2x[gr * kH + cc]);
        s.w2h[r][cc] = __float2half_rn(w2h[gr * kH + cc]);
    }
    if (tid < 64) {
        int gate = tid >> 4, u = tid & 15;
        int gr = gate * kH + hu0 + u;
        s.bL[tid] = b1x[gr] + b1h[gr];
    }
    if (tid < 48) {
        int gate = tid >> 4, u = tid & 15;
        int gr = gate * kH + hu0 + u;
        s.b2xs[tid] = b2x[gr];
        s.b2hs[tid] = b2h[gr];
    }
    // zero resident state + my slice of parity-0 global state (512 units, 1/thread)
    {
        int b = tid >> 4, u = tid & 15;
        s.c1[b][u] = 0.f;
        s.h2l[b][u] = 0.f;
        g_h1[d][0][row0 + b][hu0 + u] = __float2half_rn(0.f);
        g_h2[d][0][row0 + b][hu0 + u] = __float2half_rn(0.f);
    }
    __threadfence();
    __syncthreads();

    // ---- preload static B fragments into registers (GEMM warps 0-9) ----
    unsigned bfrag[2][16][2];
    if (w < 10) {
        #pragma unroll
        for (int sf = 0; sf < 2; sf++) {
            #pragma unroll
            for (int kk = 0; kk < 16; kk++) {
                if (w < 4)
                    ldb16x8(bfrag[sf][kk], &s.wL[(2 * w + sf) * 8][128 + kk * 16], LDW);
                else if (w < 7)
                    ldb16x8(bfrag[sf][kk], &s.w2x[(2 * (w - 4) + sf) * 8][kk * 16], LDH);
                else
                    ldb16x8(bfrag[sf][kk], &s.w2h[(2 * (w - 7) + sf) * 8][kk * 16], LDH);
            }
        }
    }
    // publish zero-init flag; stage x(0) with warps 10-15 (pre-loop, off critical path)
    if (tid == 0) st_rel(&g_flag[grp][ng][0], 1u);
    if (w >= 10)
        stage_x_192(s, x, 0, d ? (kT - 1) : 0, row0, tid - 320);
    __syncthreads();

    // ---- main recurrence: iteration k computes h1(k+1) and h2(k) ----
    for (int k = 0; k <= kT; k++) {
        const int par = k & 1;
        const int xb = k & 1;
        float acc[2][2][4] = {};   // [m-tile][strip][frag]

        if (w < 4) {
            // -------- Phase A: LSTM x-part GEMM (overlaps poll/stage) --------
            if (k < kT) {
                #pragma unroll
                for (int m = 0; m < 2; m++) {
                    #pragma unroll
                    for (int kk = 0; kk < 8; kk++) {
                        unsigned a[4];
                        lda16x16(a, &s.xbuf[xb][m * 16][kk * 16], LDX);
                        #pragma unroll
                        for (int sf = 0; sf < 2; sf++) {
                            unsigned b[2];
                            ldb16x8(b, &s.wL[(2 * w + sf) * 8][kk * 16], LDW);
                            mma16816(acc[m][sf], a, b);
                        }
                    }
                }
            }
        } else if (w < 10) {
            // -------- Phase A: GRU warps prefetch x(k+1) (otherwise idle here) ----
            if (k + 1 < kT) {
                const int t = d ? (kT - 2 - k) : (k + 1);
                stage_x_192(s, x, xb ^ 1, t, row0, tid - 128);
            }
        } else {
            const int tl = tid - 320;
            // poll group flags IMMEDIATELY (warp 10, lanes 0-15), one line per flag
            if (w == 10 && lane < 16) {
                const unsigned* fp = &g_flag[grp][lane][0];
                const unsigned ep = (unsigned)(k + 1);
                while (ld_acq(fp) < ep) { }
            }
            barn(1, 192);
            // stage h1(k) -> aH, h2(k-1) -> a2 : batched predicated unroll (MLP~12)
            {
                const uint4* s1 = (const uint4*)&g_h1[d][par][row0][0];
                const uint4* s2 = (const uint4*)&g_h2[d][par][row0][0];
                uint4 v1[6], v2[6];
                #pragma unroll
                for (int q = 0; q < 6; q++) {
                    int idx = tl + 192 * q;
                    if (idx < 1024) v1[q] = __ldcg(s1 + idx);
                }
                #pragma unroll
                for (int q = 0; q < 6; q++) {
                    int idx = tl + 192 * q;
                    if (idx < 1024) v2[q] = __ldcg(s2 + idx);
                }
                #pragma unroll
                for (int q = 0; q < 6; q++) {
                    int idx = tl + 192 * q;
                    if (idx < 1024) *((uint4*)&s.aH[idx >> 5][0] + (idx & 31)) = v1[q];
                }
                #pragma unroll
                for (int q = 0; q < 6; q++) {
                    int idx = tl + 192 * q;
                    if (idx < 1024) *((uint4*)&s.a2[idx >> 5][0] + (idx & 31)) = v2[q];
                }
            }
        }
        __syncthreads();   // sync1

        // -------- Phase B: h-dependent GEMMs (B from registers) --------
        if (w < 4) {
            if (k < kT) {
                #pragma unroll
                for (int m = 0; m < 2; m++) {
                    #pragma unroll
                    for (int kk = 0; kk < 16; kk++) {
                        unsigned a[4];
                        lda16x16(a, &s.aH[m * 16][kk * 16], LDH);
                        #pragma unroll
                        for (int sf = 0; sf < 2; sf++)
                            mma16816(acc[m][sf], a, bfrag[sf][kk]);
                    }
                }
                #pragma unroll
                for (int m = 0; m < 2; m++)
                    #pragma unroll
                    for (int sf = 0; sf < 2; sf++)
                        stacc(&s.accL[m * 16][(2 * w + sf) * 8], acc[m][sf]);
            }
        } else if (w < 10) {
            const bool isx = (w < 7);
            const int j = isx ? (w - 4) : (w - 7);
            const __half* A0 = isx ? &s.aH[0][0] : &s.a2[0][0];
            #pragma unroll
            for (int m = 0; m < 2; m++) {
                #pragma unroll
                for (int kk = 0; kk < 16; kk++) {
                    unsigned a[4];
                    lda16x16(a, A0 + (m * 16) * LDH + kk * 16, LDH);
                    #pragma unroll
                    for (int sf = 0; sf < 2; sf++)
                        mma16816(acc[m][sf], a, bfrag[sf][kk]);
                }
            }
            float* dstbase = isx ? &s.accX[0][0] : &s.accH[0][0];
            #pragma unroll
            for (int m = 0; m < 2; m++)
                #pragma unroll
                for (int sf = 0; sf < 2; sf++)
                    stacc(dstbase + (m * 16) * LDACC + (2 * j + sf) * 8, acc[m][sf]);
        }
        __syncthreads();   // sync2

        // -------- Phase C: eltwise split — w0-7 LSTM, w8-15 GRU (parallel) --------
        if (w < 8) {
            if (k < kT) {
                const int b = tid >> 3, u0 = (tid & 7) * 2;
                float h1v[2];
                #pragma unroll
                for (int q = 0; q < 2; q++) {
                    int u = u0 + q;
                    float ig = sigf(s.accL[b][u]           + s.bL[u]);
                    float fg = sigf(s.accL[b][16 + u]      + s.bL[16 + u]);
                    float gg = tanhfast(s.accL[b][32 + u]  + s.bL[32 + u]);
                    float og = sigf(s.accL[b][48 + u]      + s.bL[48 + u]);
                    float c  = s.c1[b][u] * fg + ig * gg;
                    s.c1[b][u] = c;
                    h1v[q] = og * tanhfast(c);
                }
                *(__half2*)&g_h1[d][par ^ 1][row0 + b][hu0 + u0] =
                    __floats2half2_rn(h1v[0], h1v[1]);
            }
        } else {
            const int tc = tid - 256;
            const int b = tc >> 3, u0 = (tc & 7) * 2;
            float h2v[2];
            #pragma unroll
            for (int q = 0; q < 2; q++) {
                int u = u0 + q;
                float rr = sigf(s.accX[b][u]      + s.b2xs[u]      + s.accH[b][u]      + s.b2hs[u]);
                float zz = sigf(s.accX[b][16 + u] + s.b2xs[16 + u] + s.accH[b][16 + u] + s.b2hs[16 + u]);
                float hn = s.accH[b][32 + u] + s.b2hs[32 + u];
                float nn = tanhfast(s.accX[b][32 + u] + s.b2xs[32 + u] + rr * hn);
                float h2 = zz * s.h2l[b][u] + (1.f - zz) * nn;
                s.h2l[b][u] = h2;
                h2v[q] = h2;
            }
            *(__half2*)&g_h2[d][par ^ 1][row0 + b][hu0 + u0] =
                __floats2half2_rn(h2v[0], h2v[1]);
            if (k == kT) {
                g_hf[d][row0 + b][hu0 + u0]     = h2v[0];
                g_hf[d][row0 + b][hu0 + u0 + 1] = h2v[1];
            }
        }

        __syncthreads();   // sync3 — makes all eltwise writes CTA-visible
        if (tid == 0 && k < kT) {
            __threadfence();                     // cumulativity: promote to gpu scope
            st_rel(&g_flag[grp][ng][0], (unsigned)(k + 2));
        }
        if (k == kT) break;
    }

    // ---- all-CTA barrier, reset flags for next graph replay ----
    __threadfence();
    gbar_all(2, 128);
    if (tid == 0) g_flag[grp][ng][0] = 0;

    // ---- final FC: out = [h_fwd | h_bwd] @ wo^T + bo ----
    if (blockIdx.x < 16) {
        float* sh = (float*)&s;              // reuse SMEM: [8][512]
        int b0r = blockIdx.x * 8;
        for (int idx = tid; idx < 8 * 512; idx += 512) {
            int br = idx >> 9, jj = idx & 511;
            sh[idx] = (jj < 256) ? __ldcg(&g_hf[0][b0r + br][jj])
                                 : __ldcg(&g_hf[1][b0r + br][jj - 256]);
        }
        __syncthreads();
        for (int it = tid; it < 8 * 128; it += 512) {
            int br = it >> 7, o = it & 127;
            float acc = bo[o];
            const float* wrow = wo + o * 512;
            const float* hrow = sh + br * 512;
            #pragma unroll 8
            for (int jj = 0; jj < 512; jj++) acc += hrow[jj] * wrow[jj];
            out[(size_t)(b0r + br) * kO + o] = acc;
        }
    }
}

extern "C" void kernel_launch(void* const* d_in, const int* in_sizes, int n_in,
                              void* d_out, int out_size)
{
    const float* x   = (const float*)d_in[0];
    const float* w1x = (const float*)d_in[1];
    const float* b1x = (const float*)d_in[2];
    const float* w1h = (const float*)d_in[3];
    const float* b1h = (const float*)d_in[4];
    const float* w2x = (const float*)d_in[5];
    const float* b2x = (const float*)d_in[6];
    const float* w2h = (const float*)d_in[7];
    const float* b2h = (const float*)d_in[8];
    const float* wo  = (const float*)d_in[9];
    const float* bo  = (const float*)d_in[10];

    cudaFuncSetAttribute(brnn_kernel, cudaFuncAttributeMaxDynamicSharedMemorySize,
                         (int)sizeof(SM));
    brnn_kernel<<<128, 512, sizeof(SM)>>>(x, w1x, b1x, w1h, b1h,
                                          w2x, b2x, w2h, b2h, wo, bo,
                                          (float*)d_out);
}